// round 15
// baseline (speedup 1.0000x reference)
#include <cuda_runtime.h>
#include <cuda_fp16.h>
#include <math.h>
#include <stdint.h>

// ---------------- problem constants ----------------
#define BATCH 4
#define KQ    512
#define NKV   4096
#define DMODEL 1024
#define NHEAD 16
#define HD    64
#define MQ    (BATCH*KQ)    // 2048
#define MKV   (BATCH*NKV)   // 16384
#define DFF   (4*DMODEL)    // 4096
#define KVLD  2048          // fused k|v row stride

// ---------------- scratch (device globals, no allocs) ----------------
__device__ float g_out [MQ  * DMODEL];
__device__ float g_bkv [KVLD];

__device__ __half g_qln [MQ  * DMODEL];
__device__ __half g_kvln[MKV * DMODEL];
__device__ __half g_qp  [MQ  * DMODEL];
__device__ __half g_kv  [MKV * KVLD];        // fused [k | v]
__device__ __half g_ctx [MQ  * DMODEL];
__device__ __half g_hln [MQ  * DMODEL];
__device__ __half g_m1  [MQ  * DFF];

__device__ __half g_wq [DMODEL*DMODEL];
__device__ __half g_wkv[KVLD*DMODEL];
__device__ __half g_wo [DMODEL*DMODEL];
__device__ __half g_w1 [DMODEL*DFF];
__device__ __half g_w2 [DFF*DMODEL];

// ---------------- low-level helpers ----------------
__device__ __forceinline__ uint32_t smem_u32(const void* p) {
    uint32_t a;
    asm("{ .reg .u64 t; cvta.to.shared.u64 t, %1; cvt.u32.u64 %0, t; }" : "=r"(a) : "l"(p));
    return a;
}
__device__ __forceinline__ void cpa16(uint32_t saddr, const void* g) {
    asm volatile("cp.async.cg.shared.global [%0], [%1], 16;" :: "r"(saddr), "l"(g));
}
__device__ __forceinline__ void cpa_commit() { asm volatile("cp.async.commit_group;"); }
__device__ __forceinline__ void cpa_wait1()  { asm volatile("cp.async.wait_group 1;"); }
__device__ __forceinline__ void cpa_wait0()  { asm volatile("cp.async.wait_group 0;"); }

#define LDMX4(r0, r1, r2, r3, addr) \
    asm volatile("ldmatrix.sync.aligned.m8n8.x4.shared.b16 {%0,%1,%2,%3}, [%4];" \
        : "=r"(r0), "=r"(r1), "=r"(r2), "=r"(r3) : "r"(addr))

#define LDMX4T(r0, r1, r2, r3, addr) \
    asm volatile("ldmatrix.sync.aligned.m8n8.x4.trans.shared.b16 {%0,%1,%2,%3}, [%4];" \
        : "=r"(r0), "=r"(r1), "=r"(r2), "=r"(r3) : "r"(addr))

__device__ __forceinline__ void mma_f16(float* d, const uint32_t* a, const uint32_t* b) {
    asm volatile(
        "mma.sync.aligned.m16n8k16.row.col.f32.f16.f16.f32 "
        "{%0,%1,%2,%3}, {%4,%5,%6,%7}, {%8,%9}, {%0,%1,%2,%3};"
        : "+f"(d[0]), "+f"(d[1]), "+f"(d[2]), "+f"(d[3])
        : "r"(a[0]), "r"(a[1]), "r"(a[2]), "r"(a[3]), "r"(b[0]), "r"(b[1]));
}

// 128-byte rows (64 fp16), 8 groups of 16B, xor swizzle
__device__ __forceinline__ uint32_t aoff(int row, int grp) {
    return (uint32_t)(row * 128 + ((grp ^ (row & 7)) << 4));
}

// ---------------- norm kernels ----------------
__device__ __forceinline__ void block_reduce2(float& s1, float& s2) {
    #pragma unroll
    for (int off = 16; off; off >>= 1) {
        s1 += __shfl_xor_sync(0xffffffffu, s1, off);
        s2 += __shfl_xor_sync(0xffffffffu, s2, off);
    }
    __shared__ float a[8], b[8];
    int w = threadIdx.x >> 5, lane = threadIdx.x & 31;
    if (lane == 0) { a[w] = s1; b[w] = s2; }
    __syncthreads();
    s1 = 0.f; s2 = 0.f;
    #pragma unroll
    for (int i = 0; i < 8; i++) { s1 += a[i]; s2 += b[i]; }
}

__global__ void layernorm2_k(const float* __restrict__ xq, const float* __restrict__ xkv,
                             const float* __restrict__ gq, const float* __restrict__ bq,
                             const float* __restrict__ gkv, const float* __restrict__ bkv,
                             __half* __restrict__ yq, __half* __restrict__ ykv) {
    long row = blockIdx.x;
    const float *x, *g, *b; __half* y;
    if (row < MQ) { x = xq + row * DMODEL; g = gq; b = bq; y = yq + row * DMODEL; }
    else { row -= MQ; x = xkv + row * DMODEL; g = gkv; b = bkv; y = ykv + row * DMODEL; }
    float4 xv = ((const float4*)x)[threadIdx.x];
    float s  = xv.x + xv.y + xv.z + xv.w;
    float sq = xv.x*xv.x + xv.y*xv.y + xv.z*xv.z + xv.w*xv.w;
    block_reduce2(s, sq);
    float mu  = s * (1.0f / DMODEL);
    float var = sq * (1.0f / DMODEL) - mu * mu;
    float rstd = rsqrtf(var + 1e-5f);
    float4 gv = ((const float4*)g)[threadIdx.x];
    float4 bv = ((const float4*)b)[threadIdx.x];
    __half2 a = __floats2half2_rn((xv.x - mu) * rstd * gv.x + bv.x,
                                  (xv.y - mu) * rstd * gv.y + bv.y);
    __half2 c = __floats2half2_rn((xv.z - mu) * rstd * gv.z + bv.z,
                                  (xv.w - mu) * rstd * gv.w + bv.w);
    *(__half2*)(y + threadIdx.x * 4)     = a;
    *(__half2*)(y + threadIdx.x * 4 + 2) = c;
}

__global__ void layernorm_h_k(const float* __restrict__ x, const float* __restrict__ g,
                              const float* __restrict__ b, __half* __restrict__ y) {
    long row = blockIdx.x;
    float4 xv = ((const float4*)(x + row * DMODEL))[threadIdx.x];
    float s  = xv.x + xv.y + xv.z + xv.w;
    float sq = xv.x*xv.x + xv.y*xv.y + xv.z*xv.z + xv.w*xv.w;
    block_reduce2(s, sq);
    float mu  = s * (1.0f / DMODEL);
    float var = sq * (1.0f / DMODEL) - mu * mu;
    float rstd = rsqrtf(var + 1e-5f);
    float4 gv = ((const float4*)g)[threadIdx.x];
    float4 bv = ((const float4*)b)[threadIdx.x];
    long idx = row * DMODEL + threadIdx.x * 4;
    __half2 a = __floats2half2_rn((xv.x - mu) * rstd * gv.x + bv.x,
                                  (xv.y - mu) * rstd * gv.y + bv.y);
    __half2 c = __floats2half2_rn((xv.z - mu) * rstd * gv.z + bv.z,
                                  (xv.w - mu) * rstd * gv.w + bv.w);
    *(__half2*)(y + idx)     = a;
    *(__half2*)(y + idx + 2) = c;
}

__global__ void rmsnorm2_k(__half* __restrict__ q, __half* __restrict__ kv,
                           const float* __restrict__ wq, const float* __restrict__ wk) {
    long row = blockIdx.x;
    __half* xr; const float* w;
    if (row < MQ) { xr = q + row * DMODEL; w = wq; }
    else { xr = kv + (row - MQ) * (long)KVLD; w = wk; }
    __half2 h01 = *(__half2*)(xr + threadIdx.x * 4);
    __half2 h23 = *(__half2*)(xr + threadIdx.x * 4 + 2);
    float v0 = __half2float(__low2half(h01)), v1 = __half2float(__high2half(h01));
    float v2 = __half2float(__low2half(h23)), v3 = __half2float(__high2half(h23));
    float sq = v0*v0 + v1*v1 + v2*v2 + v3*v3;
    float dummy = 0.f;
    block_reduce2(sq, dummy);
    float rstd = rsqrtf(sq * (1.0f / DMODEL) + 1e-6f);
    float4 wv = ((const float4*)w)[threadIdx.x];
    __half2 a = __floats2half2_rn(v0 * rstd * wv.x, v1 * rstd * wv.y);
    __half2 b = __floats2half2_rn(v2 * rstd * wv.z, v3 * rstd * wv.w);
    *(__half2*)(xr + threadIdx.x * 4)     = a;
    *(__half2*)(xr + threadIdx.x * 4 + 2) = b;
}

__global__ void wcvt_all_k(const float* __restrict__ Wq, const float* __restrict__ Wk,
                           const float* __restrict__ Wv, const float* __restrict__ Wo,
                           const float* __restrict__ W1, const float* __restrict__ W2,
                           __half* __restrict__ wq, __half* __restrict__ wkv,
                           __half* __restrict__ wo, __half* __restrict__ w1,
                           __half* __restrict__ w2) {
    __shared__ float ts[32][33];
    int bid = blockIdx.x;
    const float* src; __half* dst; int Kd, N;
    if      (bid <  1024) { src = Wq; dst = wq;                Kd = 1024; N = 1024; }
    else if (bid <  2048) { src = Wk; dst = wkv;               Kd = 1024; N = 1024; bid -= 1024; }
    else if (bid <  3072) { src = Wv; dst = wkv + 1024 * 1024; Kd = 1024; N = 1024; bid -= 2048; }
    else if (bid <  4096) { src = Wo; dst = wo;                Kd = 1024; N = 1024; bid -= 3072; }
    else if (bid <  8192) { src = W1; dst = w1;                Kd = 1024; N = 4096; bid -= 4096; }
    else                  { src = W2; dst = w2;                Kd = 4096; N = 1024; bid -= 8192; }
    int ntn = N >> 5;
    int n0 = (bid % ntn) << 5, k0 = (bid / ntn) << 5;
    int tx = threadIdx.x & 31, ty = threadIdx.x >> 5;
    #pragma unroll
    for (int i = 0; i < 32; i += 8)
        ts[ty + i][tx] = src[(long)(k0 + ty + i) * N + n0 + tx];
    __syncthreads();
    #pragma unroll
    for (int i = 0; i < 32; i += 8)
        dst[(long)(n0 + ty + i) * Kd + k0 + tx] = __float2half(ts[tx][ty + i]);
}

// ---------------- fp16 HMMA GEMM (4 warps, 64x64/warp, K-chunk 64, 3-stage) ----------
// EPI: 1 = fp32 out + residual, 2 = GELU -> fp16, 3 = plain fp16
#define GEMM_SMEM_BYTES (3 * 2 * 16384)   // 96KB

template<int EPI>
__global__ __launch_bounds__(128) void hgemm_k(
    const __half* __restrict__ A, const __half* __restrict__ B,
    const float* __restrict__ bias, const float* __restrict__ R,
    float* __restrict__ Cf, __half* __restrict__ Ch,
    int M, int N, int Kd)
{
    extern __shared__ char smem[];
    const uint32_t sbase = smem_u32(smem);
    const int tid = threadIdx.x;
    const int lane = tid & 31, wid = tid >> 5;
    const int wm = wid >> 1, wn = wid & 1;
    const int m0 = blockIdx.y * 128, n0 = blockIdx.x * 128;

    float acc[4][8][4] = {};
    const int nch = Kd >> 6;

    auto load_chunk = [&](int c) {
        const uint32_t stg = sbase + (c % 3) * 32768;
        const int k0 = c << 6;
        #pragma unroll
        for (int e = tid; e < 1024; e += 128) {
            int row = e >> 3, grp = e & 7;
            uint32_t so = aoff(row, grp);
            cpa16(stg +         so, A + (long)(m0 + row) * Kd + k0 + grp * 8);
            cpa16(stg + 16384 + so, B + (long)(n0 + row) * Kd + k0 + grp * 8);
        }
        cpa_commit();
    };

    load_chunk(0);
    if (nch > 1) load_chunk(1);

    const int arow = lane & 15;
    const int akh  = (lane >> 4) & 1;
    const int bn   = ((lane >> 4) & 1) * 8 + (lane & 7);
    const int bkh  = (lane >> 3) & 1;

    for (int c = 0; c < nch; ++c) {
        if (c + 1 < nch) cpa_wait1(); else cpa_wait0();
        __syncthreads();
        if (c + 2 < nch) load_chunk(c + 2);

        const uint32_t sA = sbase + (c % 3) * 32768;
        const uint32_t sB = sA + 16384;

        #pragma unroll
        for (int ks = 0; ks < 4; ++ks) {
            uint32_t bh[8][2];
            #pragma unroll
            for (int nt2 = 0; nt2 < 4; ++nt2) {
                int row = wn * 64 + nt2 * 16 + bn;
                int grp = ks * 2 + bkh;
                uint32_t so = aoff(row, grp);
                LDMX4(bh[nt2*2][0], bh[nt2*2][1], bh[nt2*2+1][0], bh[nt2*2+1][1], sB + so);
            }
            #pragma unroll
            for (int mt = 0; mt < 4; ++mt) {
                int row = wm * 64 + mt * 16 + arow;
                int grp = ks * 2 + akh;
                uint32_t so = aoff(row, grp);
                uint32_t ah[4];
                LDMX4(ah[0], ah[1], ah[2], ah[3], sA + so);
                #pragma unroll
                for (int nt = 0; nt < 8; ++nt)
                    mma_f16(acc[mt][nt], ah, bh[nt]);
            }
        }
    }

    #pragma unroll
    for (int mt = 0; mt < 4; ++mt) {
        #pragma unroll
        for (int nt = 0; nt < 8; ++nt) {
            int r0 = m0 + wm * 64 + mt * 16 + (lane >> 2);
            int c0 = n0 + wn * 64 + nt * 8 + (lane & 3) * 2;
            float b0 = bias[c0], b1 = bias[c0 + 1];
            #pragma unroll
            for (int half = 0; half < 2; ++half) {
                int row = r0 + half * 8;
                long gi = (long)row * N + c0;
                float v0 = acc[mt][nt][half * 2 + 0] + b0;
                float v1 = acc[mt][nt][half * 2 + 1] + b1;
                if (EPI == 1) {
                    float2 rv = *(const float2*)(R + gi);
                    v0 += rv.x; v1 += rv.y;
                }
                if (EPI == 2) {
                    v0 = 0.5f * v0 * (1.0f + erff(v0 * 0.7071067811865476f));
                    v1 = 0.5f * v1 * (1.0f + erff(v1 * 0.7071067811865476f));
                }
                if (EPI >= 2) {
                    __half2 ph = __floats2half2_rn(v0, v1);
                    *(__half2*)(Ch + gi) = ph;
                } else {
                    float2 o = {v0, v1};
                    *(float2*)(Cf + gi) = o;
                }
            }
        }
    }
}

// ------- HMMA flash attention (fp16 ex2 softmax, 128q x 128k tiles, 8 warps, 2-stage) -----
// grid (KQ/128, NHEAD, BATCH) = 256 CTAs, 256 threads. smem: Q 16KB + 2 x 32KB = 80KB.
#define ATT_SMEM (16384 + 2 * 32768)

__global__ __launch_bounds__(256) void flash_attn_mma(
    const __half* __restrict__ Q, const __half* __restrict__ K,
    const __half* __restrict__ V, __half* __restrict__ C)
{
    extern __shared__ char smem[];
    const uint32_t sb = smem_u32(smem);
    const int tid = threadIdx.x, lane = tid & 31, warp = tid >> 5;
    const int q0 = blockIdx.x * 128, h = blockIdx.y, b = blockIdx.z;
    const int wq0 = warp * 16;
    const float kscale = 0.125f * 1.4426950408889634f;

    const uint32_t sQ = sb;

    {
        const long gq = (long)(b * KQ + q0) * DMODEL + h * HD;
        for (int e = tid; e < 1024; e += 256) {
            int row = e >> 3, grp = e & 7;
            cpa16(sQ + aoff(row, grp), Q + gq + (long)row * DMODEL + grp * 8);
        }
    }
    #define LOAD_KV(it_) do { \
        const uint32_t st_ = sb + 16384 + ((it_) & 1) * 32768; \
        const long gk_ = (long)(b * NKV + (it_) * 128) * KVLD + h * HD; \
        for (int e = tid; e < 1024; e += 256) { \
            int row = e >> 3, grp = e & 7; \
            long g = gk_ + (long)row * KVLD + grp * 8; \
            uint32_t so = aoff(row, grp); \
            cpa16(st_ +         so, K + g); \
            cpa16(st_ + 16384 + so, V + g); \
        } \
        cpa_commit(); \
    } while (0)

    LOAD_KV(0);

    uint32_t qf[4][4];
    float ctx[8][4] = {};
    float m0 = -INFINITY, m1 = -INFINITY, l0 = 0.f, l1 = 0.f;

    const int NIT = NKV / 128;
    for (int it = 0; it < NIT; ++it) {
        cpa_wait0();
        __syncthreads();
        if (it == 0) {
            int row = wq0 + (lane & 15);
            #pragma unroll
            for (int ks = 0; ks < 4; ++ks) {
                int grp = ks * 2 + ((lane >> 4) & 1);
                uint32_t so = aoff(row, grp);
                LDMX4(qf[ks][0], qf[ks][1], qf[ks][2], qf[ks][3], sQ + so);
            }
        }
        if (it + 1 < NIT) LOAD_KV(it + 1);

        const uint32_t st = sb + 16384 + (it & 1) * 32768;
        const uint32_t sk = st, sv = st + 16384;

        float S[16][4] = {};
        #pragma unroll
        for (int ks = 0; ks < 4; ++ks) {
            uint32_t bh[16][2];
            #pragma unroll
            for (int kp = 0; kp < 8; ++kp) {
                int row = kp * 16 + ((lane >> 4) & 1) * 8 + (lane & 7);
                int grp = ks * 2 + ((lane >> 3) & 1);
                uint32_t so = aoff(row, grp);
                LDMX4(bh[2*kp][0], bh[2*kp][1], bh[2*kp+1][0], bh[2*kp+1][1], sk + so);
            }
            #pragma unroll
            for (int nt = 0; nt < 16; ++nt)
                mma_f16(S[nt], qf[ks], bh[nt]);
        }

        float mx0 = -INFINITY, mx1 = -INFINITY;
        #pragma unroll
        for (int nt = 0; nt < 16; ++nt) {
            mx0 = fmaxf(mx0, fmaxf(S[nt][0], S[nt][1]));
            mx1 = fmaxf(mx1, fmaxf(S[nt][2], S[nt][3]));
        }
        mx0 = fmaxf(mx0, __shfl_xor_sync(0xffffffffu, mx0, 1));
        mx0 = fmaxf(mx0, __shfl_xor_sync(0xffffffffu, mx0, 2));
        mx1 = fmaxf(mx1, __shfl_xor_sync(0xffffffffu, mx1, 1));
        mx1 = fmaxf(mx1, __shfl_xor_sync(0xffffffffu, mx1, 2));
        float m0n = fmaxf(m0, mx0), m1n = fmaxf(m1, mx1);
        float cr0 = exp2f((m0 - m0n) * kscale), cr1 = exp2f((m1 - m1n) * kscale);
        float nm0 = -m0n * kscale, nm1 = -m1n * kscale;

        uint32_t pa[8][4];
        float s0 = 0.f, s1 = 0.f;
        #pragma unroll
        for (int j = 0; j < 8; ++j) {
            __half2 e; float2 f;
            e = h2exp2(__floats2half2_rn(fmaf(S[2*j][0],   kscale, nm0),
                                         fmaf(S[2*j][1],   kscale, nm0)));
            pa[j][0] = *(uint32_t*)&e; f = __half22float2(e); s0 += f.x + f.y;
            e = h2exp2(__floats2half2_rn(fmaf(S[2*j][2],   kscale, nm1),
                                         fmaf(S[2*j][3],   kscale, nm1)));
            pa[j][1] = *(uint32_t*)&e; f = __half22float2(e); s1 += f.x + f.y;
            e = h2exp2(__floats2half2_rn(fmaf(S[2*j+1][0], kscale, nm0),
                                         fmaf(S[2*j+1][1], kscale, nm0)));
            pa[j][2] = *(uint32_t*)&e; f = __half22float2(e); s0 += f.x + f.y;
            e = h2exp2(__floats2half2_rn(fmaf(S[2*j+1][2], kscale, nm1),
                                         fmaf(S[2*j+1][3], kscale, nm1)));
            pa[j][3] = *(uint32_t*)&e; f = __half22float2(e); s1 += f.x + f.y;
        }
        s0 += __shfl_xor_sync(0xffffffffu, s0, 1);
        s0 += __shfl_xor_sync(0xffffffffu, s0, 2);
        s1 += __shfl_xor_sync(0xffffffffu, s1, 1);
        s1 += __shfl_xor_sync(0xffffffffu, s1, 2);
        l0 = l0 * cr0 + s0;  l1 = l1 * cr1 + s1;
        m0 = m0n;  m1 = m1n;
        #pragma unroll
        for (int dt = 0; dt < 8; ++dt) {
            ctx[dt][0] *= cr0; ctx[dt][1] *= cr0;
            ctx[dt][2] *= cr1; ctx[dt][3] *= cr1;
        }

        #pragma unroll
        for (int ks = 0; ks < 8; ++ks) {
            uint32_t vb[8][2];
            #pragma unroll
            for (int dp = 0; dp < 4; ++dp) {
                int row = ks * 16 + ((lane >> 3) & 1) * 8 + (lane & 7);
                int grp = dp * 2 + ((lane >> 4) & 1);
                uint32_t so = aoff(row, grp);
                LDMX4T(vb[2*dp][0], vb[2*dp][1], vb[2*dp+1][0], vb[2*dp+1][1], sv + so);
            }
            #pragma unroll
            for (int dt = 0; dt < 8; ++dt)
                mma_f16(ctx[dt], pa[ks], vb[dt]);
        }
    }

    float i0 = 1.f / l0, i1 = 1.f / l1;
    int r0 = q0 + wq0 + (lane >> 2);
    int r1 = r0 + 8;
    #pragma unroll
    for (int dt = 0; dt < 8; ++dt) {
        int col = h * HD + dt * 8 + (lane & 3) * 2;
        long g0 = (long)(b * KQ + r0) * DMODEL + col;
        long g1 = (long)(b * KQ + r1) * DMODEL + col;
        __half2 p0 = __floats2half2_rn(ctx[dt][0] * i0, ctx[dt][1] * i0);
        __half2 p1 = __floats2half2_rn(ctx[dt][2] * i1, ctx[dt][3] * i1);
        *(__half2*)(C + g0) = p0;
        *(__half2*)(C + g1) = p1;
    }
    #undef LOAD_KV
}

// ---------------- launch ----------------
extern "C" void kernel_launch(void* const* d_in, const int* in_sizes, int n_in,
                              void* d_out, int out_size) {
    const float* query_tokens   = (const float*)d_in[0];
    const float* point_features = (const float*)d_in[1];
    const float* ln_q_g  = (const float*)d_in[2];
    const float* ln_q_b  = (const float*)d_in[3];
    const float* ln_kv_g = (const float*)d_in[4];
    const float* ln_kv_b = (const float*)d_in[5];
    const float* Wq = (const float*)d_in[6];   const float* bq = (const float*)d_in[7];
    const float* Wk = (const float*)d_in[8];   const float* bk = (const float*)d_in[9];
    const float* Wv = (const float*)d_in[10];  const float* bv = (const float*)d_in[11];
    const float* rms_q_w = (const float*)d_in[12];
    const float* rms_k_w = (const float*)d_in[13];
    const float* Wo = (const float*)d_in[14];  const float* bo = (const float*)d_in[15];
    const float* ln_mlp_g = (const float*)d_in[16];
    const float* ln_mlp_b = (const float*)d_in[17];
    const float* W1 = (const float*)d_in[18];  const float* b1 = (const float*)d_in[19];
    const float* W2 = (const float*)d_in[20];  const float* b2 = (const float*)d_in[21];
    float* out = (float*)d_out;

    float *p_out, *p_bkv;
    cudaGetSymbolAddress((void**)&p_out, g_out);
    cudaGetSymbolAddress((void**)&p_bkv, g_bkv);

    __half *qln,*kvln,*ctx,*hln,*m1,*qp,*kv;
    __half *wq,*wkv,*wo,*w1,*w2;
    cudaGetSymbolAddress((void**)&qln, g_qln);  cudaGetSymbolAddress((void**)&kvln, g_kvln);
    cudaGetSymbolAddress((void**)&ctx, g_ctx);  cudaGetSymbolAddress((void**)&hln, g_hln);
    cudaGetSymbolAddress((void**)&m1, g_m1);
    cudaGetSymbolAddress((void**)&qp, g_qp);    cudaGetSymbolAddress((void**)&kv, g_kv);
    cudaGetSymbolAddress((void**)&wq, g_wq);    cudaGetSymbolAddress((void**)&wkv, g_wkv);
    cudaGetSymbolAddress((void**)&wo, g_wo);
    cudaGetSymbolAddress((void**)&w1, g_w1);    cudaGetSymbolAddress((void**)&w2, g_w2);

    cudaFuncSetAttribute(hgemm_k<1>, cudaFuncAttributeMaxDynamicSharedMemorySize, GEMM_SMEM_BYTES);
    cudaFuncSetAttribute(hgemm_k<2>, cudaFuncAttributeMaxDynamicSharedMemorySize, GEMM_SMEM_BYTES);
    cudaFuncSetAttribute(hgemm_k<3>, cudaFuncAttributeMaxDynamicSharedMemorySize, GEMM_SMEM_BYTES);
    cudaFuncSetAttribute(flash_attn_mma, cudaFuncAttributeMaxDynamicSharedMemorySize, ATT_SMEM);

    static cudaStream_t s1 = nullptr;
    static cudaEvent_t evA = nullptr, evB = nullptr, evC = nullptr, evD = nullptr;
    if (s1 == nullptr) {
        cudaStreamCreateWithFlags(&s1, cudaStreamNonBlocking);
        cudaEventCreateWithFlags(&evA, cudaEventDisableTiming);
        cudaEventCreateWithFlags(&evB, cudaEventDisableTiming);
        cudaEventCreateWithFlags(&evC, cudaEventDisableTiming);
        cudaEventCreateWithFlags(&evD, cudaEventDisableTiming);
    }

    cudaMemcpyAsync(p_bkv,        bk, DMODEL * sizeof(float), cudaMemcpyDeviceToDevice);
    cudaMemcpyAsync(p_bkv + 1024, bv, DMODEL * sizeof(float), cudaMemcpyDeviceToDevice);

    // fork: wcvt on s1 || layernorm2 on main
    cudaEventRecord(evA, 0);
    cudaStreamWaitEvent(s1, evA, 0);
    wcvt_all_k<<<12288, 256, 0, s1>>>(Wq, Wk, Wv, Wo, W1, W2, wq, wkv, wo, w1, w2);
    layernorm2_k<<<MQ + MKV, 256>>>(query_tokens, point_features,
                                    ln_q_g, ln_q_b, ln_kv_g, ln_kv_b, qln, kvln);
    // join, then fork: Q proj on s1 || KV proj on main
    cudaEventRecord(evB, s1);
    cudaStreamWaitEvent(0, evB, 0);
    cudaEventRecord(evC, 0);
    cudaStreamWaitEvent(s1, evC, 0);
    hgemm_k<3><<<dim3(DMODEL/128, MQ/128), 128, GEMM_SMEM_BYTES, s1>>>(
        qln, wq, bq, nullptr, nullptr, qp, MQ, DMODEL, DMODEL);
    hgemm_k<3><<<dim3(KVLD/128, MKV/128), 128, GEMM_SMEM_BYTES>>>(
        kvln, wkv, p_bkv, nullptr, nullptr, kv, MKV, KVLD, DMODEL);
    cudaEventRecord(evD, s1);
    cudaStreamWaitEvent(0, evD, 0);

    rmsnorm2_k<<<MQ + MKV, 256>>>(qp, kv, rms_q_w, rms_k_w);

    flash_attn_mma<<<dim3(KQ/128, NHEAD, BATCH), 256, ATT_SMEM>>>(qp, kv, kv + 1024, ctx);

    hgemm_k<1><<<dim3(DMODEL/128, MQ/128), 128, GEMM_SMEM_BYTES>>>(
        ctx, wo, bo, query_tokens, p_out, nullptr, MQ, DMODEL, DMODEL);

    layernorm_h_k<<<MQ, 256>>>(p_out, ln_mlp_g, ln_mlp_b, hln);
    hgemm_k<2><<<dim3(DFF/128, MQ/128), 128, GEMM_SMEM_BYTES>>>(
        hln, w1, b1, nullptr, nullptr, m1, MQ, DFF, DMODEL);
    hgemm_k<1><<<dim3(DMODEL/128, MQ/128), 128, GEMM_SMEM_BYTES>>>(
        m1, w2, b2, p_out, out, nullptr, MQ, DMODEL, DFF);
}

// round 16
// speedup vs baseline: 1.0072x; 1.0072x over previous
#include <cuda_runtime.h>
#include <cuda_fp16.h>
#include <math.h>
#include <stdint.h>

// ---------------- problem constants ----------------
#define BATCH 4
#define KQ    512
#define NKV   4096
#define DMODEL 1024
#define NHEAD 16
#define HD    64
#define MQ    (BATCH*KQ)    // 2048
#define MKV   (BATCH*NKV)   // 16384
#define DFF   (4*DMODEL)    // 4096
#define KVLD  2048          // fused k|v row stride

// ---------------- scratch (device globals, no allocs) ----------------
__device__ float g_out [MQ  * DMODEL];
__device__ float g_bkv [KVLD];

__device__ __half g_qln [MQ  * DMODEL];
__device__ __half g_kvln[MKV * DMODEL];
__device__ __half g_qp  [MQ  * DMODEL];
__device__ __half g_kv  [MKV * KVLD];        // fused [k | v]
__device__ __half g_ctx [MQ  * DMODEL];
__device__ __half g_hln [MQ  * DMODEL];
__device__ __half g_m1  [MQ  * DFF];

__device__ __half g_wq [DMODEL*DMODEL];
__device__ __half g_wkv[KVLD*DMODEL];
__device__ __half g_wo [DMODEL*DMODEL];
__device__ __half g_w1 [DMODEL*DFF];
__device__ __half g_w2 [DFF*DMODEL];

// ---------------- low-level helpers ----------------
__device__ __forceinline__ uint32_t smem_u32(const void* p) {
    uint32_t a;
    asm("{ .reg .u64 t; cvta.to.shared.u64 t, %1; cvt.u32.u64 %0, t; }" : "=r"(a) : "l"(p));
    return a;
}
__device__ __forceinline__ void cpa16(uint32_t saddr, const void* g) {
    asm volatile("cp.async.cg.shared.global [%0], [%1], 16;" :: "r"(saddr), "l"(g));
}
__device__ __forceinline__ void cpa_commit() { asm volatile("cp.async.commit_group;"); }
__device__ __forceinline__ void cpa_wait1()  { asm volatile("cp.async.wait_group 1;"); }
__device__ __forceinline__ void cpa_wait0()  { asm volatile("cp.async.wait_group 0;"); }

#define LDMX4(r0, r1, r2, r3, addr) \
    asm volatile("ldmatrix.sync.aligned.m8n8.x4.shared.b16 {%0,%1,%2,%3}, [%4];" \
        : "=r"(r0), "=r"(r1), "=r"(r2), "=r"(r3) : "r"(addr))

#define LDMX4T(r0, r1, r2, r3, addr) \
    asm volatile("ldmatrix.sync.aligned.m8n8.x4.trans.shared.b16 {%0,%1,%2,%3}, [%4];" \
        : "=r"(r0), "=r"(r1), "=r"(r2), "=r"(r3) : "r"(addr))

__device__ __forceinline__ void mma_f16(float* d, const uint32_t* a, const uint32_t* b) {
    asm volatile(
        "mma.sync.aligned.m16n8k16.row.col.f32.f16.f16.f32 "
        "{%0,%1,%2,%3}, {%4,%5,%6,%7}, {%8,%9}, {%0,%1,%2,%3};"
        : "+f"(d[0]), "+f"(d[1]), "+f"(d[2]), "+f"(d[3])
        : "r"(a[0]), "r"(a[1]), "r"(a[2]), "r"(a[3]), "r"(b[0]), "r"(b[1]));
}

// 128-byte rows (64 fp16), 8 groups of 16B, xor swizzle
__device__ __forceinline__ uint32_t aoff(int row, int grp) {
    return (uint32_t)(row * 128 + ((grp ^ (row & 7)) << 4));
}

// ---------------- norm kernels ----------------
__device__ __forceinline__ void block_reduce2(float& s1, float& s2) {
    #pragma unroll
    for (int off = 16; off; off >>= 1) {
        s1 += __shfl_xor_sync(0xffffffffu, s1, off);
        s2 += __shfl_xor_sync(0xffffffffu, s2, off);
    }
    __shared__ float a[8], b[8];
    int w = threadIdx.x >> 5, lane = threadIdx.x & 31;
    if (lane == 0) { a[w] = s1; b[w] = s2; }
    __syncthreads();
    s1 = 0.f; s2 = 0.f;
    #pragma unroll
    for (int i = 0; i < 8; i++) { s1 += a[i]; s2 += b[i]; }
}

__global__ void layernorm2_k(const float* __restrict__ xq, const float* __restrict__ xkv,
                             const float* __restrict__ gq, const float* __restrict__ bq,
                             const float* __restrict__ gkv, const float* __restrict__ bkv,
                             __half* __restrict__ yq, __half* __restrict__ ykv) {
    long row = blockIdx.x;
    const float *x, *g, *b; __half* y;
    if (row < MQ) { x = xq + row * DMODEL; g = gq; b = bq; y = yq + row * DMODEL; }
    else { row -= MQ; x = xkv + row * DMODEL; g = gkv; b = bkv; y = ykv + row * DMODEL; }
    float4 xv = ((const float4*)x)[threadIdx.x];
    float s  = xv.x + xv.y + xv.z + xv.w;
    float sq = xv.x*xv.x + xv.y*xv.y + xv.z*xv.z + xv.w*xv.w;
    block_reduce2(s, sq);
    float mu  = s * (1.0f / DMODEL);
    float var = sq * (1.0f / DMODEL) - mu * mu;
    float rstd = rsqrtf(var + 1e-5f);
    float4 gv = ((const float4*)g)[threadIdx.x];
    float4 bv = ((const float4*)b)[threadIdx.x];
    __half2 a = __floats2half2_rn((xv.x - mu) * rstd * gv.x + bv.x,
                                  (xv.y - mu) * rstd * gv.y + bv.y);
    __half2 c = __floats2half2_rn((xv.z - mu) * rstd * gv.z + bv.z,
                                  (xv.w - mu) * rstd * gv.w + bv.w);
    *(__half2*)(y + threadIdx.x * 4)     = a;
    *(__half2*)(y + threadIdx.x * 4 + 2) = c;
}

__global__ void layernorm_h_k(const float* __restrict__ x, const float* __restrict__ g,
                              const float* __restrict__ b, __half* __restrict__ y) {
    long row = blockIdx.x;
    float4 xv = ((const float4*)(x + row * DMODEL))[threadIdx.x];
    float s  = xv.x + xv.y + xv.z + xv.w;
    float sq = xv.x*xv.x + xv.y*xv.y + xv.z*xv.z + xv.w*xv.w;
    block_reduce2(s, sq);
    float mu  = s * (1.0f / DMODEL);
    float var = sq * (1.0f / DMODEL) - mu * mu;
    float rstd = rsqrtf(var + 1e-5f);
    float4 gv = ((const float4*)g)[threadIdx.x];
    float4 bv = ((const float4*)b)[threadIdx.x];
    long idx = row * DMODEL + threadIdx.x * 4;
    __half2 a = __floats2half2_rn((xv.x - mu) * rstd * gv.x + bv.x,
                                  (xv.y - mu) * rstd * gv.y + bv.y);
    __half2 c = __floats2half2_rn((xv.z - mu) * rstd * gv.z + bv.z,
                                  (xv.w - mu) * rstd * gv.w + bv.w);
    *(__half2*)(y + idx)     = a;
    *(__half2*)(y + idx + 2) = c;
}

__global__ void rmsnorm2_k(__half* __restrict__ q, __half* __restrict__ kv,
                           const float* __restrict__ wq, const float* __restrict__ wk) {
    long row = blockIdx.x;
    __half* xr; const float* w;
    if (row < MQ) { xr = q + row * DMODEL; w = wq; }
    else { xr = kv + (row - MQ) * (long)KVLD; w = wk; }
    __half2 h01 = *(__half2*)(xr + threadIdx.x * 4);
    __half2 h23 = *(__half2*)(xr + threadIdx.x * 4 + 2);
    float v0 = __half2float(__low2half(h01)), v1 = __half2float(__high2half(h01));
    float v2 = __half2float(__low2half(h23)), v3 = __half2float(__high2half(h23));
    float sq = v0*v0 + v1*v1 + v2*v2 + v3*v3;
    float dummy = 0.f;
    block_reduce2(sq, dummy);
    float rstd = rsqrtf(sq * (1.0f / DMODEL) + 1e-6f);
    float4 wv = ((const float4*)w)[threadIdx.x];
    __half2 a = __floats2half2_rn(v0 * rstd * wv.x, v1 * rstd * wv.y);
    __half2 b = __floats2half2_rn(v2 * rstd * wv.z, v3 * rstd * wv.w);
    *(__half2*)(xr + threadIdx.x * 4)     = a;
    *(__half2*)(xr + threadIdx.x * 4 + 2) = b;
}

__global__ void wcvt_all_k(const float* __restrict__ Wq, const float* __restrict__ Wk,
                           const float* __restrict__ Wv, const float* __restrict__ Wo,
                           const float* __restrict__ W1, const float* __restrict__ W2,
                           __half* __restrict__ wq, __half* __restrict__ wkv,
                           __half* __restrict__ wo, __half* __restrict__ w1,
                           __half* __restrict__ w2) {
    __shared__ float ts[32][33];
    int bid = blockIdx.x;
    const float* src; __half* dst; int Kd, N;
    if      (bid <  1024) { src = Wq; dst = wq;                Kd = 1024; N = 1024; }
    else if (bid <  2048) { src = Wk; dst = wkv;               Kd = 1024; N = 1024; bid -= 1024; }
    else if (bid <  3072) { src = Wv; dst = wkv + 1024 * 1024; Kd = 1024; N = 1024; bid -= 2048; }
    else if (bid <  4096) { src = Wo; dst = wo;                Kd = 1024; N = 1024; bid -= 3072; }
    else if (bid <  8192) { src = W1; dst = w1;                Kd = 1024; N = 4096; bid -= 4096; }
    else                  { src = W2; dst = w2;                Kd = 4096; N = 1024; bid -= 8192; }
    int ntn = N >> 5;
    int n0 = (bid % ntn) << 5, k0 = (bid / ntn) << 5;
    int tx = threadIdx.x & 31, ty = threadIdx.x >> 5;
    #pragma unroll
    for (int i = 0; i < 32; i += 8)
        ts[ty + i][tx] = src[(long)(k0 + ty + i) * N + n0 + tx];
    __syncthreads();
    #pragma unroll
    for (int i = 0; i < 32; i += 8)
        dst[(long)(n0 + ty + i) * Kd + k0 + tx] = __float2half(ts[tx][ty + i]);
}

// ---------------- fp16 HMMA GEMM (4 warps, 64x64/warp, K-chunk 64, 3-stage) ----------
// EPI: 1 = fp32 out + residual, 2 = GELU -> fp16, 3 = plain fp16
#define GEMM_SMEM_BYTES (3 * 2 * 16384)   // 96KB

template<int EPI>
__global__ __launch_bounds__(128) void hgemm_k(
    const __half* __restrict__ A, const __half* __restrict__ B,
    const float* __restrict__ bias, const float* __restrict__ R,
    float* __restrict__ Cf, __half* __restrict__ Ch,
    int M, int N, int Kd)
{
    extern __shared__ char smem[];
    const uint32_t sbase = smem_u32(smem);
    const int tid = threadIdx.x;
    const int lane = tid & 31, wid = tid >> 5;
    const int wm = wid >> 1, wn = wid & 1;
    const int m0 = blockIdx.y * 128, n0 = blockIdx.x * 128;

    float acc[4][8][4] = {};
    const int nch = Kd >> 6;

    auto load_chunk = [&](int c) {
        const uint32_t stg = sbase + (c % 3) * 32768;
        const int k0 = c << 6;
        #pragma unroll
        for (int e = tid; e < 1024; e += 128) {
            int row = e >> 3, grp = e & 7;
            uint32_t so = aoff(row, grp);
            cpa16(stg +         so, A + (long)(m0 + row) * Kd + k0 + grp * 8);
            cpa16(stg + 16384 + so, B + (long)(n0 + row) * Kd + k0 + grp * 8);
        }
        cpa_commit();
    };

    load_chunk(0);
    if (nch > 1) load_chunk(1);

    const int arow = lane & 15;
    const int akh  = (lane >> 4) & 1;
    const int bn   = ((lane >> 4) & 1) * 8 + (lane & 7);
    const int bkh  = (lane >> 3) & 1;

    for (int c = 0; c < nch; ++c) {
        if (c + 1 < nch) cpa_wait1(); else cpa_wait0();
        __syncthreads();
        if (c + 2 < nch) load_chunk(c + 2);

        const uint32_t sA = sbase + (c % 3) * 32768;
        const uint32_t sB = sA + 16384;

        #pragma unroll
        for (int ks = 0; ks < 4; ++ks) {
            uint32_t bh[8][2];
            #pragma unroll
            for (int nt2 = 0; nt2 < 4; ++nt2) {
                int row = wn * 64 + nt2 * 16 + bn;
                int grp = ks * 2 + bkh;
                uint32_t so = aoff(row, grp);
                LDMX4(bh[nt2*2][0], bh[nt2*2][1], bh[nt2*2+1][0], bh[nt2*2+1][1], sB + so);
            }
            #pragma unroll
            for (int mt = 0; mt < 4; ++mt) {
                int row = wm * 64 + mt * 16 + arow;
                int grp = ks * 2 + akh;
                uint32_t so = aoff(row, grp);
                uint32_t ah[4];
                LDMX4(ah[0], ah[1], ah[2], ah[3], sA + so);
                #pragma unroll
                for (int nt = 0; nt < 8; ++nt)
                    mma_f16(acc[mt][nt], ah, bh[nt]);
            }
        }
    }

    #pragma unroll
    for (int mt = 0; mt < 4; ++mt) {
        #pragma unroll
        for (int nt = 0; nt < 8; ++nt) {
            int r0 = m0 + wm * 64 + mt * 16 + (lane >> 2);
            int c0 = n0 + wn * 64 + nt * 8 + (lane & 3) * 2;
            float b0 = bias[c0], b1 = bias[c0 + 1];
            #pragma unroll
            for (int half = 0; half < 2; ++half) {
                int row = r0 + half * 8;
                long gi = (long)row * N + c0;
                float v0 = acc[mt][nt][half * 2 + 0] + b0;
                float v1 = acc[mt][nt][half * 2 + 1] + b1;
                if (EPI == 1) {
                    float2 rv = *(const float2*)(R + gi);
                    v0 += rv.x; v1 += rv.y;
                }
                if (EPI == 2) {
                    v0 = 0.5f * v0 * (1.0f + erff(v0 * 0.7071067811865476f));
                    v1 = 0.5f * v1 * (1.0f + erff(v1 * 0.7071067811865476f));
                }
                if (EPI >= 2) {
                    __half2 ph = __floats2half2_rn(v0, v1);
                    *(__half2*)(Ch + gi) = ph;
                } else {
                    float2 o = {v0, v1};
                    *(float2*)(Cf + gi) = o;
                }
            }
        }
    }
}

// ---------------- wide fp16 HMMA GEMM: CTA 128x256, 8 warps (2x4), K-chunk 64, 2-stage ----
// Used for W1 (GELU epilogue). smem: 2 x (16KB A + 32KB B) = 96KB.
__global__ __launch_bounds__(256) void hgemm_wide_gelu_k(
    const __half* __restrict__ A, const __half* __restrict__ B,
    const float* __restrict__ bias, __half* __restrict__ Ch,
    int M, int N, int Kd)
{
    extern __shared__ char smem[];
    const uint32_t sbase = smem_u32(smem);
    const int tid = threadIdx.x;
    const int lane = tid & 31, wid = tid >> 5;
    const int wm = wid >> 2, wn = wid & 3;          // warp grid 2x4, each 64x64
    const int m0 = blockIdx.y * 128, n0 = blockIdx.x * 256;

    float acc[4][8][4] = {};
    const int nch = Kd >> 6;

    auto load_chunk = [&](int c) {
        const uint32_t stg = sbase + (c & 1) * 49152;
        const int k0 = c << 6;
        #pragma unroll
        for (int e = tid; e < 3072; e += 256) {
            if (e < 1024) {
                int row = e >> 3, grp = e & 7;
                cpa16(stg + aoff(row, grp), A + (long)(m0 + row) * Kd + k0 + grp * 8);
            } else {
                int e2 = e - 1024;
                int row = e2 >> 3, grp = e2 & 7;
                cpa16(stg + 16384 + aoff(row, grp), B + (long)(n0 + row) * Kd + k0 + grp * 8);
            }
        }
        cpa_commit();
    };

    load_chunk(0);
    if (nch > 1) load_chunk(1);

    const int arow = lane & 15;
    const int akh  = (lane >> 4) & 1;
    const int bn   = ((lane >> 4) & 1) * 8 + (lane & 7);
    const int bkh  = (lane >> 3) & 1;

    for (int c = 0; c < nch; ++c) {
        if (c + 1 < nch) cpa_wait1(); else cpa_wait0();
        __syncthreads();

        const uint32_t sA = sbase + (c & 1) * 49152;
        const uint32_t sB = sA + 16384;

        #pragma unroll
        for (int ks = 0; ks < 4; ++ks) {
            uint32_t bh[8][2];
            #pragma unroll
            for (int nt2 = 0; nt2 < 4; ++nt2) {
                int row = wn * 64 + nt2 * 16 + bn;
                int grp = ks * 2 + bkh;
                uint32_t so = aoff(row, grp);
                LDMX4(bh[nt2*2][0], bh[nt2*2][1], bh[nt2*2+1][0], bh[nt2*2+1][1], sB + so);
            }
            #pragma unroll
            for (int mt = 0; mt < 4; ++mt) {
                int row = wm * 64 + mt * 16 + arow;
                int grp = ks * 2 + akh;
                uint32_t so = aoff(row, grp);
                uint32_t ah[4];
                LDMX4(ah[0], ah[1], ah[2], ah[3], sA + so);
                #pragma unroll
                for (int nt = 0; nt < 8; ++nt)
                    mma_f16(acc[mt][nt], ah, bh[nt]);
            }
        }
        __syncthreads();
        if (c + 2 < nch) load_chunk(c + 2);
    }

    #pragma unroll
    for (int mt = 0; mt < 4; ++mt) {
        #pragma unroll
        for (int nt = 0; nt < 8; ++nt) {
            int r0 = m0 + wm * 64 + mt * 16 + (lane >> 2);
            int c0 = n0 + wn * 64 + nt * 8 + (lane & 3) * 2;
            float b0 = bias[c0], b1 = bias[c0 + 1];
            #pragma unroll
            for (int half = 0; half < 2; ++half) {
                int row = r0 + half * 8;
                long gi = (long)row * N + c0;
                float v0 = acc[mt][nt][half * 2 + 0] + b0;
                float v1 = acc[mt][nt][half * 2 + 1] + b1;
                v0 = 0.5f * v0 * (1.0f + erff(v0 * 0.7071067811865476f));
                v1 = 0.5f * v1 * (1.0f + erff(v1 * 0.7071067811865476f));
                __half2 ph = __floats2half2_rn(v0, v1);
                *(__half2*)(Ch + gi) = ph;
            }
        }
    }
}

// ---------------- HMMA flash attention (fp16 ex2 softmax, 64q x 128k, 2-stage) --------
#define ATT_SMEM (8192 + 2 * 32768)

__global__ __launch_bounds__(128) void flash_attn_mma(
    const __half* __restrict__ Q, const __half* __restrict__ K,
    const __half* __restrict__ V, __half* __restrict__ C)
{
    extern __shared__ char smem[];
    const uint32_t sb = smem_u32(smem);
    const int tid = threadIdx.x, lane = tid & 31, warp = tid >> 5;
    const int q0 = blockIdx.x * 64, h = blockIdx.y, b = blockIdx.z;
    const int wq0 = warp * 16;
    const float kscale = 0.125f * 1.4426950408889634f;

    const uint32_t sQ = sb;

    {
        const long gq = (long)(b * KQ + q0) * DMODEL + h * HD;
        for (int e = tid; e < 512; e += 128) {
            int row = e >> 3, grp = e & 7;
            cpa16(sQ + aoff(row, grp), Q + gq + (long)row * DMODEL + grp * 8);
        }
    }
    #define LOAD_KV(it_) do { \
        const uint32_t st_ = sb + 8192 + ((it_) & 1) * 32768; \
        const long gk_ = (long)(b * NKV + (it_) * 128) * KVLD + h * HD; \
        for (int e = tid; e < 1024; e += 128) { \
            int row = e >> 3, grp = e & 7; \
            long g = gk_ + (long)row * KVLD + grp * 8; \
            uint32_t so = aoff(row, grp); \
            cpa16(st_ +         so, K + g); \
            cpa16(st_ + 16384 + so, V + g); \
        } \
        cpa_commit(); \
    } while (0)

    LOAD_KV(0);

    uint32_t qf[4][4];
    float ctx[8][4] = {};
    float m0 = -INFINITY, m1 = -INFINITY, l0 = 0.f, l1 = 0.f;

    const int NIT = NKV / 128;
    for (int it = 0; it < NIT; ++it) {
        cpa_wait0();
        __syncthreads();
        if (it == 0) {
            int row = wq0 + (lane & 15);
            #pragma unroll
            for (int ks = 0; ks < 4; ++ks) {
                int grp = ks * 2 + ((lane >> 4) & 1);
                uint32_t so = aoff(row, grp);
                LDMX4(qf[ks][0], qf[ks][1], qf[ks][2], qf[ks][3], sQ + so);
            }
        }
        if (it + 1 < NIT) LOAD_KV(it + 1);

        const uint32_t st = sb + 8192 + (it & 1) * 32768;
        const uint32_t sk = st, sv = st + 16384;

        float S[16][4] = {};
        #pragma unroll
        for (int ks = 0; ks < 4; ++ks) {
            uint32_t bh[16][2];
            #pragma unroll
            for (int kp = 0; kp < 8; ++kp) {
                int row = kp * 16 + ((lane >> 4) & 1) * 8 + (lane & 7);
                int grp = ks * 2 + ((lane >> 3) & 1);
                uint32_t so = aoff(row, grp);
                LDMX4(bh[2*kp][0], bh[2*kp][1], bh[2*kp+1][0], bh[2*kp+1][1], sk + so);
            }
            #pragma unroll
            for (int nt = 0; nt < 16; ++nt)
                mma_f16(S[nt], qf[ks], bh[nt]);
        }

        float mx0 = -INFINITY, mx1 = -INFINITY;
        #pragma unroll
        for (int nt = 0; nt < 16; ++nt) {
            mx0 = fmaxf(mx0, fmaxf(S[nt][0], S[nt][1]));
            mx1 = fmaxf(mx1, fmaxf(S[nt][2], S[nt][3]));
        }
        mx0 = fmaxf(mx0, __shfl_xor_sync(0xffffffffu, mx0, 1));
        mx0 = fmaxf(mx0, __shfl_xor_sync(0xffffffffu, mx0, 2));
        mx1 = fmaxf(mx1, __shfl_xor_sync(0xffffffffu, mx1, 1));
        mx1 = fmaxf(mx1, __shfl_xor_sync(0xffffffffu, mx1, 2));
        float m0n = fmaxf(m0, mx0), m1n = fmaxf(m1, mx1);
        float cr0 = exp2f((m0 - m0n) * kscale), cr1 = exp2f((m1 - m1n) * kscale);
        float nm0 = -m0n * kscale, nm1 = -m1n * kscale;

        uint32_t pa[8][4];
        float s0 = 0.f, s1 = 0.f;
        #pragma unroll
        for (int j = 0; j < 8; ++j) {
            __half2 e; float2 f;
            e = h2exp2(__floats2half2_rn(fmaf(S[2*j][0],   kscale, nm0),
                                         fmaf(S[2*j][1],   kscale, nm0)));
            pa[j][0] = *(uint32_t*)&e; f = __half22float2(e); s0 += f.x + f.y;
            e = h2exp2(__floats2half2_rn(fmaf(S[2*j][2],   kscale, nm1),
                                         fmaf(S[2*j][3],   kscale, nm1)));
            pa[j][1] = *(uint32_t*)&e; f = __half22float2(e); s1 += f.x + f.y;
            e = h2exp2(__floats2half2_rn(fmaf(S[2*j+1][0], kscale, nm0),
                                         fmaf(S[2*j+1][1], kscale, nm0)));
            pa[j][2] = *(uint32_t*)&e; f = __half22float2(e); s0 += f.x + f.y;
            e = h2exp2(__floats2half2_rn(fmaf(S[2*j+1][2], kscale, nm1),
                                         fmaf(S[2*j+1][3], kscale, nm1)));
            pa[j][3] = *(uint32_t*)&e; f = __half22float2(e); s1 += f.x + f.y;
        }
        s0 += __shfl_xor_sync(0xffffffffu, s0, 1);
        s0 += __shfl_xor_sync(0xffffffffu, s0, 2);
        s1 += __shfl_xor_sync(0xffffffffu, s1, 1);
        s1 += __shfl_xor_sync(0xffffffffu, s1, 2);
        l0 = l0 * cr0 + s0;  l1 = l1 * cr1 + s1;
        m0 = m0n;  m1 = m1n;
        #pragma unroll
        for (int dt = 0; dt < 8; ++dt) {
            ctx[dt][0] *= cr0; ctx[dt][1] *= cr0;
            ctx[dt][2] *= cr1; ctx[dt][3] *= cr1;
        }

        #pragma unroll
        for (int ks = 0; ks < 8; ++ks) {
            uint32_t vb[8][2];
            #pragma unroll
            for (int dp = 0; dp < 4; ++dp) {
                int row = ks * 16 + ((lane >> 3) & 1) * 8 + (lane & 7);
                int grp = dp * 2 + ((lane >> 4) & 1);
                uint32_t so = aoff(row, grp);
                LDMX4T(vb[2*dp][0], vb[2*dp][1], vb[2*dp+1][0], vb[2*dp+1][1], sv + so);
            }
            #pragma unroll
            for (int dt = 0; dt < 8; ++dt)
                mma_f16(ctx[dt], pa[ks], vb[dt]);
        }
    }

    float i0 = 1.f / l0, i1 = 1.f / l1;
    int r0 = q0 + wq0 + (lane >> 2);
    int r1 = r0 + 8;
    #pragma unroll
    for (int dt = 0; dt < 8; ++dt) {
        int col = h * HD + dt * 8 + (lane & 3) * 2;
        long g0 = (long)(b * KQ + r0) * DMODEL + col;
        long g1 = (long)(b * KQ + r1) * DMODEL + col;
        __half2 p0 = __floats2half2_rn(ctx[dt][0] * i0, ctx[dt][1] * i0);
        __half2 p1 = __floats2half2_rn(ctx[dt][2] * i1, ctx[dt][3] * i1);
        *(__half2*)(C + g0) = p0;
        *(__half2*)(C + g1) = p1;
    }
    #undef LOAD_KV
}

// ---------------- launch ----------------
extern "C" void kernel_launch(void* const* d_in, const int* in_sizes, int n_in,
                              void* d_out, int out_size) {
    const float* query_tokens   = (const float*)d_in[0];
    const float* point_features = (const float*)d_in[1];
    const float* ln_q_g  = (const float*)d_in[2];
    const float* ln_q_b  = (const float*)d_in[3];
    const float* ln_kv_g = (const float*)d_in[4];
    const float* ln_kv_b = (const float*)d_in[5];
    const float* Wq = (const float*)d_in[6];   const float* bq = (const float*)d_in[7];
    const float* Wk = (const float*)d_in[8];   const float* bk = (const float*)d_in[9];
    const float* Wv = (const float*)d_in[10];  const float* bv = (const float*)d_in[11];
    const float* rms_q_w = (const float*)d_in[12];
    const float* rms_k_w = (const float*)d_in[13];
    const float* Wo = (const float*)d_in[14];  const float* bo = (const float*)d_in[15];
    const float* ln_mlp_g = (const float*)d_in[16];
    const float* ln_mlp_b = (const float*)d_in[17];
    const float* W1 = (const float*)d_in[18];  const float* b1 = (const float*)d_in[19];
    const float* W2 = (const float*)d_in[20];  const float* b2 = (const float*)d_in[21];
    float* out = (float*)d_out;

    float *p_out, *p_bkv;
    cudaGetSymbolAddress((void**)&p_out, g_out);
    cudaGetSymbolAddress((void**)&p_bkv, g_bkv);

    __half *qln,*kvln,*ctx,*hln,*m1,*qp,*kv;
    __half *wq,*wkv,*wo,*w1,*w2;
    cudaGetSymbolAddress((void**)&qln, g_qln);  cudaGetSymbolAddress((void**)&kvln, g_kvln);
    cudaGetSymbolAddress((void**)&ctx, g_ctx);  cudaGetSymbolAddress((void**)&hln, g_hln);
    cudaGetSymbolAddress((void**)&m1, g_m1);
    cudaGetSymbolAddress((void**)&qp, g_qp);    cudaGetSymbolAddress((void**)&kv, g_kv);
    cudaGetSymbolAddress((void**)&wq, g_wq);    cudaGetSymbolAddress((void**)&wkv, g_wkv);
    cudaGetSymbolAddress((void**)&wo, g_wo);
    cudaGetSymbolAddress((void**)&w1, g_w1);    cudaGetSymbolAddress((void**)&w2, g_w2);

    cudaFuncSetAttribute(hgemm_k<1>, cudaFuncAttributeMaxDynamicSharedMemorySize, GEMM_SMEM_BYTES);
    cudaFuncSetAttribute(hgemm_k<3>, cudaFuncAttributeMaxDynamicSharedMemorySize, GEMM_SMEM_BYTES);
    cudaFuncSetAttribute(hgemm_wide_gelu_k, cudaFuncAttributeMaxDynamicSharedMemorySize, GEMM_SMEM_BYTES);
    cudaFuncSetAttribute(flash_attn_mma, cudaFuncAttributeMaxDynamicSharedMemorySize, ATT_SMEM);

    static cudaStream_t s1 = nullptr;
    static cudaEvent_t evA = nullptr, evB = nullptr, evC = nullptr, evD = nullptr;
    if (s1 == nullptr) {
        cudaStreamCreateWithFlags(&s1, cudaStreamNonBlocking);
        cudaEventCreateWithFlags(&evA, cudaEventDisableTiming);
        cudaEventCreateWithFlags(&evB, cudaEventDisableTiming);
        cudaEventCreateWithFlags(&evC, cudaEventDisableTiming);
        cudaEventCreateWithFlags(&evD, cudaEventDisableTiming);
    }

    cudaMemcpyAsync(p_bkv,        bk, DMODEL * sizeof(float), cudaMemcpyDeviceToDevice);
    cudaMemcpyAsync(p_bkv + 1024, bv, DMODEL * sizeof(float), cudaMemcpyDeviceToDevice);

    // fork: wcvt on s1 || layernorm2 on main
    cudaEventRecord(evA, 0);
    cudaStreamWaitEvent(s1, evA, 0);
    wcvt_all_k<<<12288, 256, 0, s1>>>(Wq, Wk, Wv, Wo, W1, W2, wq, wkv, wo, w1, w2);
    layernorm2_k<<<MQ + MKV, 256>>>(query_tokens, point_features,
                                    ln_q_g, ln_q_b, ln_kv_g, ln_kv_b, qln, kvln);
    // join, then fork: Q proj on s1 || KV proj on main
    cudaEventRecord(evB, s1);
    cudaStreamWaitEvent(0, evB, 0);
    cudaEventRecord(evC, 0);
    cudaStreamWaitEvent(s1, evC, 0);
    hgemm_k<3><<<dim3(DMODEL/128, MQ/128), 128, GEMM_SMEM_BYTES, s1>>>(
        qln, wq, bq, nullptr, nullptr, qp, MQ, DMODEL, DMODEL);
    hgemm_k<3><<<dim3(KVLD/128, MKV/128), 128, GEMM_SMEM_BYTES>>>(
        kvln, wkv, p_bkv, nullptr, nullptr, kv, MKV, KVLD, DMODEL);
    cudaEventRecord(evD, s1);
    cudaStreamWaitEvent(0, evD, 0);

    rmsnorm2_k<<<MQ + MKV, 256>>>(qp, kv, rms_q_w, rms_k_w);

    flash_attn_mma<<<dim3(KQ/64, NHEAD, BATCH), 128, ATT_SMEM>>>(qp, kv, kv + 1024, ctx);

    hgemm_k<1><<<dim3(DMODEL/128, MQ/128), 128, GEMM_SMEM_BYTES>>>(
        ctx, wo, bo, query_tokens, p_out, nullptr, MQ, DMODEL, DMODEL);

    layernorm_h_k<<<MQ, 256>>>(p_out, ln_mlp_g, ln_mlp_b, hln);
    hgemm_wide_gelu_k<<<dim3(DFF/256, MQ/128), 256, GEMM_SMEM_BYTES>>>(
        hln, w1, b1, m1, MQ, DFF, DMODEL);
    hgemm_k<1><<<dim3(DMODEL/128, MQ/128), 128, GEMM_SMEM_BYTES>>>(
        m1, w2, b2, p_out, out, nullptr, MQ, DMODEL, DFF);
}

// round 17
// speedup vs baseline: 1.0364x; 1.0290x over previous
#include <cuda_runtime.h>
#include <cuda_fp16.h>
#include <math.h>
#include <stdint.h>

// ---------------- problem constants ----------------
#define BATCH 4
#define KQ    512
#define NKV   4096
#define DMODEL 1024
#define NHEAD 16
#define HD    64
#define MQ    (BATCH*KQ)    // 2048
#define MKV   (BATCH*NKV)   // 16384
#define DFF   (4*DMODEL)    // 4096
#define KVLD  2048          // fused k|v row stride

// ---------------- scratch (device globals, no allocs) ----------------
__device__ float g_out [MQ  * DMODEL];
__device__ float g_bkv [KVLD];

__device__ __half g_qln [MQ  * DMODEL];
__device__ __half g_kvln[MKV * DMODEL];
__device__ __half g_qp  [MQ  * DMODEL];
__device__ __half g_kv  [MKV * KVLD];        // fused [k | v]
__device__ __half g_ctx [MQ  * DMODEL];
__device__ __half g_hln [MQ  * DMODEL];
__device__ __half g_m1  [MQ  * DFF];

__device__ __half g_wq [DMODEL*DMODEL];
__device__ __half g_wkv[KVLD*DMODEL];
__device__ __half g_wo [DMODEL*DMODEL];
__device__ __half g_w1 [DMODEL*DFF];
__device__ __half g_w2 [DFF*DMODEL];

// ---------------- low-level helpers ----------------
__device__ __forceinline__ uint32_t smem_u32(const void* p) {
    uint32_t a;
    asm("{ .reg .u64 t; cvta.to.shared.u64 t, %1; cvt.u32.u64 %0, t; }" : "=r"(a) : "l"(p));
    return a;
}
__device__ __forceinline__ void cpa16(uint32_t saddr, const void* g) {
    asm volatile("cp.async.cg.shared.global [%0], [%1], 16;" :: "r"(saddr), "l"(g));
}
__device__ __forceinline__ void cpa_commit() { asm volatile("cp.async.commit_group;"); }
__device__ __forceinline__ void cpa_wait1()  { asm volatile("cp.async.wait_group 1;"); }
__device__ __forceinline__ void cpa_wait0()  { asm volatile("cp.async.wait_group 0;"); }

#define LDMX4(r0, r1, r2, r3, addr) \
    asm volatile("ldmatrix.sync.aligned.m8n8.x4.shared.b16 {%0,%1,%2,%3}, [%4];" \
        : "=r"(r0), "=r"(r1), "=r"(r2), "=r"(r3) : "r"(addr))

#define LDMX4T(r0, r1, r2, r3, addr) \
    asm volatile("ldmatrix.sync.aligned.m8n8.x4.trans.shared.b16 {%0,%1,%2,%3}, [%4];" \
        : "=r"(r0), "=r"(r1), "=r"(r2), "=r"(r3) : "r"(addr))

__device__ __forceinline__ void mma_f16(float* d, const uint32_t* a, const uint32_t* b) {
    asm volatile(
        "mma.sync.aligned.m16n8k16.row.col.f32.f16.f16.f32 "
        "{%0,%1,%2,%3}, {%4,%5,%6,%7}, {%8,%9}, {%0,%1,%2,%3};"
        : "+f"(d[0]), "+f"(d[1]), "+f"(d[2]), "+f"(d[3])
        : "r"(a[0]), "r"(a[1]), "r"(a[2]), "r"(a[3]), "r"(b[0]), "r"(b[1]));
}

// 128-byte rows (64 fp16), 8 groups of 16B, xor swizzle
__device__ __forceinline__ uint32_t aoff(int row, int grp) {
    return (uint32_t)(row * 128 + ((grp ^ (row & 7)) << 4));
}

// ---------------- norm kernels ----------------
__device__ __forceinline__ void block_reduce2(float& s1, float& s2) {
    #pragma unroll
    for (int off = 16; off; off >>= 1) {
        s1 += __shfl_xor_sync(0xffffffffu, s1, off);
        s2 += __shfl_xor_sync(0xffffffffu, s2, off);
    }
    __shared__ float a[8], b[8];
    int w = threadIdx.x >> 5, lane = threadIdx.x & 31;
    if (lane == 0) { a[w] = s1; b[w] = s2; }
    __syncthreads();
    s1 = 0.f; s2 = 0.f;
    #pragma unroll
    for (int i = 0; i < 8; i++) { s1 += a[i]; s2 += b[i]; }
}

__global__ void layernorm2_k(const float* __restrict__ xq, const float* __restrict__ xkv,
                             const float* __restrict__ gq, const float* __restrict__ bq,
                             const float* __restrict__ gkv, const float* __restrict__ bkv,
                             __half* __restrict__ yq, __half* __restrict__ ykv) {
    long row = blockIdx.x;
    const float *x, *g, *b; __half* y;
    if (row < MQ) { x = xq + row * DMODEL; g = gq; b = bq; y = yq + row * DMODEL; }
    else { row -= MQ; x = xkv + row * DMODEL; g = gkv; b = bkv; y = ykv + row * DMODEL; }
    float4 xv = ((const float4*)x)[threadIdx.x];
    float s  = xv.x + xv.y + xv.z + xv.w;
    float sq = xv.x*xv.x + xv.y*xv.y + xv.z*xv.z + xv.w*xv.w;
    block_reduce2(s, sq);
    float mu  = s * (1.0f / DMODEL);
    float var = sq * (1.0f / DMODEL) - mu * mu;
    float rstd = rsqrtf(var + 1e-5f);
    float4 gv = ((const float4*)g)[threadIdx.x];
    float4 bv = ((const float4*)b)[threadIdx.x];
    __half2 a = __floats2half2_rn((xv.x - mu) * rstd * gv.x + bv.x,
                                  (xv.y - mu) * rstd * gv.y + bv.y);
    __half2 c = __floats2half2_rn((xv.z - mu) * rstd * gv.z + bv.z,
                                  (xv.w - mu) * rstd * gv.w + bv.w);
    *(__half2*)(y + threadIdx.x * 4)     = a;
    *(__half2*)(y + threadIdx.x * 4 + 2) = c;
}

__global__ void layernorm_h_k(const float* __restrict__ x, const float* __restrict__ g,
                              const float* __restrict__ b, __half* __restrict__ y) {
    long row = blockIdx.x;
    float4 xv = ((const float4*)(x + row * DMODEL))[threadIdx.x];
    float s  = xv.x + xv.y + xv.z + xv.w;
    float sq = xv.x*xv.x + xv.y*xv.y + xv.z*xv.z + xv.w*xv.w;
    block_reduce2(s, sq);
    float mu  = s * (1.0f / DMODEL);
    float var = sq * (1.0f / DMODEL) - mu * mu;
    float rstd = rsqrtf(var + 1e-5f);
    float4 gv = ((const float4*)g)[threadIdx.x];
    float4 bv = ((const float4*)b)[threadIdx.x];
    long idx = row * DMODEL + threadIdx.x * 4;
    __half2 a = __floats2half2_rn((xv.x - mu) * rstd * gv.x + bv.x,
                                  (xv.y - mu) * rstd * gv.y + bv.y);
    __half2 c = __floats2half2_rn((xv.z - mu) * rstd * gv.z + bv.z,
                                  (xv.w - mu) * rstd * gv.w + bv.w);
    *(__half2*)(y + idx)     = a;
    *(__half2*)(y + idx + 2) = c;
}

// rmsnorm over rows [0, nrows) of x with row stride ld (in-place)
__global__ void rmsnorm_k(__half* __restrict__ x, const float* __restrict__ w, int ld) {
    long row = blockIdx.x;
    __half* xr = x + row * (long)ld;
    __half2 h01 = *(__half2*)(xr + threadIdx.x * 4);
    __half2 h23 = *(__half2*)(xr + threadIdx.x * 4 + 2);
    float v0 = __half2float(__low2half(h01)), v1 = __half2float(__high2half(h01));
    float v2 = __half2float(__low2half(h23)), v3 = __half2float(__high2half(h23));
    float sq = v0*v0 + v1*v1 + v2*v2 + v3*v3;
    float dummy = 0.f;
    block_reduce2(sq, dummy);
    float rstd = rsqrtf(sq * (1.0f / DMODEL) + 1e-6f);
    float4 wv = ((const float4*)w)[threadIdx.x];
    __half2 a = __floats2half2_rn(v0 * rstd * wv.x, v1 * rstd * wv.y);
    __half2 b = __floats2half2_rn(v2 * rstd * wv.z, v3 * rstd * wv.w);
    *(__half2*)(xr + threadIdx.x * 4)     = a;
    *(__half2*)(xr + threadIdx.x * 4 + 2) = b;
}

__global__ void wcvt_all_k(const float* __restrict__ Wq, const float* __restrict__ Wk,
                           const float* __restrict__ Wv, const float* __restrict__ Wo,
                           const float* __restrict__ W1, const float* __restrict__ W2,
                           __half* __restrict__ wq, __half* __restrict__ wkv,
                           __half* __restrict__ wo, __half* __restrict__ w1,
                           __half* __restrict__ w2) {
    __shared__ float ts[32][33];
    int bid = blockIdx.x;
    const float* src; __half* dst; int Kd, N;
    if      (bid <  1024) { src = Wq; dst = wq;                Kd = 1024; N = 1024; }
    else if (bid <  2048) { src = Wk; dst = wkv;               Kd = 1024; N = 1024; bid -= 1024; }
    else if (bid <  3072) { src = Wv; dst = wkv + 1024 * 1024; Kd = 1024; N = 1024; bid -= 2048; }
    else if (bid <  4096) { src = Wo; dst = wo;                Kd = 1024; N = 1024; bid -= 3072; }
    else if (bid <  8192) { src = W1; dst = w1;                Kd = 1024; N = 4096; bid -= 4096; }
    else                  { src = W2; dst = w2;                Kd = 4096; N = 1024; bid -= 8192; }
    int ntn = N >> 5;
    int n0 = (bid % ntn) << 5, k0 = (bid / ntn) << 5;
    int tx = threadIdx.x & 31, ty = threadIdx.x >> 5;
    #pragma unroll
    for (int i = 0; i < 32; i += 8)
        ts[ty + i][tx] = src[(long)(k0 + ty + i) * N + n0 + tx];
    __syncthreads();
    #pragma unroll
    for (int i = 0; i < 32; i += 8)
        dst[(long)(n0 + ty + i) * Kd + k0 + tx] = __float2half(ts[tx][ty + i]);
}

// ---------------- fp16 HMMA GEMM (4 warps, 64x64/warp, K-chunk 64, 3-stage) ----------
// EPI: 1 = fp32 out + residual, 2 = GELU -> fp16, 3 = plain fp16
#define GEMM_SMEM_BYTES (3 * 2 * 16384)   // 96KB

template<int EPI>
__global__ __launch_bounds__(128) void hgemm_k(
    const __half* __restrict__ A, const __half* __restrict__ B,
    const float* __restrict__ bias, const float* __restrict__ R,
    float* __restrict__ Cf, __half* __restrict__ Ch,
    int M, int N, int Kd)
{
    extern __shared__ char smem[];
    const uint32_t sbase = smem_u32(smem);
    const int tid = threadIdx.x;
    const int lane = tid & 31, wid = tid >> 5;
    const int wm = wid >> 1, wn = wid & 1;
    const int m0 = blockIdx.y * 128, n0 = blockIdx.x * 128;

    float acc[4][8][4] = {};
    const int nch = Kd >> 6;

    auto load_chunk = [&](int c) {
        const uint32_t stg = sbase + (c % 3) * 32768;
        const int k0 = c << 6;
        #pragma unroll
        for (int e = tid; e < 1024; e += 128) {
            int row = e >> 3, grp = e & 7;
            uint32_t so = aoff(row, grp);
            cpa16(stg +         so, A + (long)(m0 + row) * Kd + k0 + grp * 8);
            cpa16(stg + 16384 + so, B + (long)(n0 + row) * Kd + k0 + grp * 8);
        }
        cpa_commit();
    };

    load_chunk(0);
    if (nch > 1) load_chunk(1);

    const int arow = lane & 15;
    const int akh  = (lane >> 4) & 1;
    const int bn   = ((lane >> 4) & 1) * 8 + (lane & 7);
    const int bkh  = (lane >> 3) & 1;

    for (int c = 0; c < nch; ++c) {
        if (c + 1 < nch) cpa_wait1(); else cpa_wait0();
        __syncthreads();
        if (c + 2 < nch) load_chunk(c + 2);

        const uint32_t sA = sbase + (c % 3) * 32768;
        const uint32_t sB = sA + 16384;

        #pragma unroll
        for (int ks = 0; ks < 4; ++ks) {
            uint32_t bh[8][2];
            #pragma unroll
            for (int nt2 = 0; nt2 < 4; ++nt2) {
                int row = wn * 64 + nt2 * 16 + bn;
                int grp = ks * 2 + bkh;
                uint32_t so = aoff(row, grp);
                LDMX4(bh[nt2*2][0], bh[nt2*2][1], bh[nt2*2+1][0], bh[nt2*2+1][1], sB + so);
            }
            #pragma unroll
            for (int mt = 0; mt < 4; ++mt) {
                int row = wm * 64 + mt * 16 + arow;
                int grp = ks * 2 + akh;
                uint32_t so = aoff(row, grp);
                uint32_t ah[4];
                LDMX4(ah[0], ah[1], ah[2], ah[3], sA + so);
                #pragma unroll
                for (int nt = 0; nt < 8; ++nt)
                    mma_f16(acc[mt][nt], ah, bh[nt]);
            }
        }
    }

    #pragma unroll
    for (int mt = 0; mt < 4; ++mt) {
        #pragma unroll
        for (int nt = 0; nt < 8; ++nt) {
            int r0 = m0 + wm * 64 + mt * 16 + (lane >> 2);
            int c0 = n0 + wn * 64 + nt * 8 + (lane & 3) * 2;
            float b0 = bias[c0], b1 = bias[c0 + 1];
            #pragma unroll
            for (int half = 0; half < 2; ++half) {
                int row = r0 + half * 8;
                long gi = (long)row * N + c0;
                float v0 = acc[mt][nt][half * 2 + 0] + b0;
                float v1 = acc[mt][nt][half * 2 + 1] + b1;
                if (EPI == 1) {
                    float2 rv = *(const float2*)(R + gi);
                    v0 += rv.x; v1 += rv.y;
                }
                if (EPI == 2) {
                    v0 = 0.5f * v0 * (1.0f + erff(v0 * 0.7071067811865476f));
                    v1 = 0.5f * v1 * (1.0f + erff(v1 * 0.7071067811865476f));
                }
                if (EPI >= 2) {
                    __half2 ph = __floats2half2_rn(v0, v1);
                    *(__half2*)(Ch + gi) = ph;
                } else {
                    float2 o = {v0, v1};
                    *(float2*)(Cf + gi) = o;
                }
            }
        }
    }
}

// ---------------- HMMA flash attention (fp16 ex2 softmax, 64q x 128k, 3-stage) --------
// grid (KQ/64, NHEAD, BATCH) = 512 CTAs, 128 threads. smem: Q 8KB + 3 x 32KB = 104KB.
#define ATT_SMEM (8192 + 3 * 32768)

__global__ __launch_bounds__(128) void flash_attn_mma(
    const __half* __restrict__ Q, const __half* __restrict__ K,
    const __half* __restrict__ V, __half* __restrict__ C)
{
    extern __shared__ char smem[];
    const uint32_t sb = smem_u32(smem);
    const int tid = threadIdx.x, lane = tid & 31, warp = tid >> 5;
    const int q0 = blockIdx.x * 64, h = blockIdx.y, b = blockIdx.z;
    const int wq0 = warp * 16;
    const float kscale = 0.125f * 1.4426950408889634f;

    const uint32_t sQ = sb;

    {
        const long gq = (long)(b * KQ + q0) * DMODEL + h * HD;
        for (int e = tid; e < 512; e += 128) {
            int row = e >> 3, grp = e & 7;
            cpa16(sQ + aoff(row, grp), Q + gq + (long)row * DMODEL + grp * 8);
        }
    }
    #define LOAD_KV(it_) do { \
        const uint32_t st_ = sb + 8192 + ((it_) % 3) * 32768; \
        const long gk_ = (long)(b * NKV + (it_) * 128) * KVLD + h * HD; \
        for (int e = tid; e < 1024; e += 128) { \
            int row = e >> 3, grp = e & 7; \
            long g = gk_ + (long)row * KVLD + grp * 8; \
            uint32_t so = aoff(row, grp); \
            cpa16(st_ +         so, K + g); \
            cpa16(st_ + 16384 + so, V + g); \
        } \
        cpa_commit(); \
    } while (0)

    LOAD_KV(0);
    LOAD_KV(1);

    uint32_t qf[4][4];
    float ctx[8][4] = {};
    float m0 = -INFINITY, m1 = -INFINITY, l0 = 0.f, l1 = 0.f;

    const int NIT = NKV / 128;   // 32
    for (int it = 0; it < NIT; ++it) {
        if (it + 1 < NIT) cpa_wait1(); else cpa_wait0();
        __syncthreads();
        if (it == 0) {
            int row = wq0 + (lane & 15);
            #pragma unroll
            for (int ks = 0; ks < 4; ++ks) {
                int grp = ks * 2 + ((lane >> 4) & 1);
                uint32_t so = aoff(row, grp);
                LDMX4(qf[ks][0], qf[ks][1], qf[ks][2], qf[ks][3], sQ + so);
            }
        }
        if (it + 2 < NIT) LOAD_KV(it + 2);

        const uint32_t st = sb + 8192 + (it % 3) * 32768;
        const uint32_t sk = st, sv = st + 16384;

        float S[16][4] = {};
        #pragma unroll
        for (int ks = 0; ks < 4; ++ks) {
            uint32_t bh[16][2];
            #pragma unroll
            for (int kp = 0; kp < 8; ++kp) {
                int row = kp * 16 + ((lane >> 4) & 1) * 8 + (lane & 7);
                int grp = ks * 2 + ((lane >> 3) & 1);
                uint32_t so = aoff(row, grp);
                LDMX4(bh[2*kp][0], bh[2*kp][1], bh[2*kp+1][0], bh[2*kp+1][1], sk + so);
            }
            #pragma unroll
            for (int nt = 0; nt < 16; ++nt)
                mma_f16(S[nt], qf[ks], bh[nt]);
        }

        float mx0 = -INFINITY, mx1 = -INFINITY;
        #pragma unroll
        for (int nt = 0; nt < 16; ++nt) {
            mx0 = fmaxf(mx0, fmaxf(S[nt][0], S[nt][1]));
            mx1 = fmaxf(mx1, fmaxf(S[nt][2], S[nt][3]));
        }
        mx0 = fmaxf(mx0, __shfl_xor_sync(0xffffffffu, mx0, 1));
        mx0 = fmaxf(mx0, __shfl_xor_sync(0xffffffffu, mx0, 2));
        mx1 = fmaxf(mx1, __shfl_xor_sync(0xffffffffu, mx1, 1));
        mx1 = fmaxf(mx1, __shfl_xor_sync(0xffffffffu, mx1, 2));
        float m0n = fmaxf(m0, mx0), m1n = fmaxf(m1, mx1);
        float cr0 = exp2f((m0 - m0n) * kscale), cr1 = exp2f((m1 - m1n) * kscale);
        float nm0 = -m0n * kscale, nm1 = -m1n * kscale;

        uint32_t pa[8][4];
        float s0 = 0.f, s1 = 0.f;
        #pragma unroll
        for (int j = 0; j < 8; ++j) {
            __half2 e; float2 f;
            e = h2exp2(__floats2half2_rn(fmaf(S[2*j][0],   kscale, nm0),
                                         fmaf(S[2*j][1],   kscale, nm0)));
            pa[j][0] = *(uint32_t*)&e; f = __half22float2(e); s0 += f.x + f.y;
            e = h2exp2(__floats2half2_rn(fmaf(S[2*j][2],   kscale, nm1),
                                         fmaf(S[2*j][3],   kscale, nm1)));
            pa[j][1] = *(uint32_t*)&e; f = __half22float2(e); s1 += f.x + f.y;
            e = h2exp2(__floats2half2_rn(fmaf(S[2*j+1][0], kscale, nm0),
                                         fmaf(S[2*j+1][1], kscale, nm0)));
            pa[j][2] = *(uint32_t*)&e; f = __half22float2(e); s0 += f.x + f.y;
            e = h2exp2(__floats2half2_rn(fmaf(S[2*j+1][2], kscale, nm1),
                                         fmaf(S[2*j+1][3], kscale, nm1)));
            pa[j][3] = *(uint32_t*)&e; f = __half22float2(e); s1 += f.x + f.y;
        }
        s0 += __shfl_xor_sync(0xffffffffu, s0, 1);
        s0 += __shfl_xor_sync(0xffffffffu, s0, 2);
        s1 += __shfl_xor_sync(0xffffffffu, s1, 1);
        s1 += __shfl_xor_sync(0xffffffffu, s1, 2);
        l0 = l0 * cr0 + s0;  l1 = l1 * cr1 + s1;
        m0 = m0n;  m1 = m1n;
        #pragma unroll
        for (int dt = 0; dt < 8; ++dt) {
            ctx[dt][0] *= cr0; ctx[dt][1] *= cr0;
            ctx[dt][2] *= cr1; ctx[dt][3] *= cr1;
        }

        #pragma unroll
        for (int ks = 0; ks < 8; ++ks) {
            uint32_t vb[8][2];
            #pragma unroll
            for (int dp = 0; dp < 4; ++dp) {
                int row = ks * 16 + ((lane >> 3) & 1) * 8 + (lane & 7);
                int grp = dp * 2 + ((lane >> 4) & 1);
                uint32_t so = aoff(row, grp);
                LDMX4T(vb[2*dp][0], vb[2*dp][1], vb[2*dp+1][0], vb[2*dp+1][1], sv + so);
            }
            #pragma unroll
            for (int dt = 0; dt < 8; ++dt)
                mma_f16(ctx[dt], pa[ks], vb[dt]);
        }
    }

    float i0 = 1.f / l0, i1 = 1.f / l1;
    int r0 = q0 + wq0 + (lane >> 2);
    int r1 = r0 + 8;
    #pragma unroll
    for (int dt = 0; dt < 8; ++dt) {
        int col = h * HD + dt * 8 + (lane & 3) * 2;
        long g0 = (long)(b * KQ + r0) * DMODEL + col;
        long g1 = (long)(b * KQ + r1) * DMODEL + col;
        __half2 p0 = __floats2half2_rn(ctx[dt][0] * i0, ctx[dt][1] * i0);
        __half2 p1 = __floats2half2_rn(ctx[dt][2] * i1, ctx[dt][3] * i1);
        *(__half2*)(C + g0) = p0;
        *(__half2*)(C + g1) = p1;
    }
    #undef LOAD_KV
}

// ---------------- launch ----------------
extern "C" void kernel_launch(void* const* d_in, const int* in_sizes, int n_in,
                              void* d_out, int out_size) {
    const float* query_tokens   = (const float*)d_in[0];
    const float* point_features = (const float*)d_in[1];
    const float* ln_q_g  = (const float*)d_in[2];
    const float* ln_q_b  = (const float*)d_in[3];
    const float* ln_kv_g = (const float*)d_in[4];
    const float* ln_kv_b = (const float*)d_in[5];
    const float* Wq = (const float*)d_in[6];   const float* bq = (const float*)d_in[7];
    const float* Wk = (const float*)d_in[8];   const float* bk = (const float*)d_in[9];
    const float* Wv = (const float*)d_in[10];  const float* bv = (const float*)d_in[11];
    const float* rms_q_w = (const float*)d_in[12];
    const float* rms_k_w = (const float*)d_in[13];
    const float* Wo = (const float*)d_in[14];  const float* bo = (const float*)d_in[15];
    const float* ln_mlp_g = (const float*)d_in[16];
    const float* ln_mlp_b = (const float*)d_in[17];
    const float* W1 = (const float*)d_in[18];  const float* b1 = (const float*)d_in[19];
    const float* W2 = (const float*)d_in[20];  const float* b2 = (const float*)d_in[21];
    float* out = (float*)d_out;

    float *p_out, *p_bkv;
    cudaGetSymbolAddress((void**)&p_out, g_out);
    cudaGetSymbolAddress((void**)&p_bkv, g_bkv);

    __half *qln,*kvln,*ctx,*hln,*m1,*qp,*kv;
    __half *wq,*wkv,*wo,*w1,*w2;
    cudaGetSymbolAddress((void**)&qln, g_qln);  cudaGetSymbolAddress((void**)&kvln, g_kvln);
    cudaGetSymbolAddress((void**)&ctx, g_ctx);  cudaGetSymbolAddress((void**)&hln, g_hln);
    cudaGetSymbolAddress((void**)&m1, g_m1);
    cudaGetSymbolAddress((void**)&qp, g_qp);    cudaGetSymbolAddress((void**)&kv, g_kv);
    cudaGetSymbolAddress((void**)&wq, g_wq);    cudaGetSymbolAddress((void**)&wkv, g_wkv);
    cudaGetSymbolAddress((void**)&wo, g_wo);
    cudaGetSymbolAddress((void**)&w1, g_w1);    cudaGetSymbolAddress((void**)&w2, g_w2);

    cudaFuncSetAttribute(hgemm_k<1>, cudaFuncAttributeMaxDynamicSharedMemorySize, GEMM_SMEM_BYTES);
    cudaFuncSetAttribute(hgemm_k<2>, cudaFuncAttributeMaxDynamicSharedMemorySize, GEMM_SMEM_BYTES);
    cudaFuncSetAttribute(hgemm_k<3>, cudaFuncAttributeMaxDynamicSharedMemorySize, GEMM_SMEM_BYTES);
    cudaFuncSetAttribute(flash_attn_mma, cudaFuncAttributeMaxDynamicSharedMemorySize, ATT_SMEM);

    static cudaStream_t s1 = nullptr;
    static cudaEvent_t evA = nullptr, evB = nullptr, evC = nullptr, evD = nullptr;
    if (s1 == nullptr) {
        cudaStreamCreateWithFlags(&s1, cudaStreamNonBlocking);
        cudaEventCreateWithFlags(&evA, cudaEventDisableTiming);
        cudaEventCreateWithFlags(&evB, cudaEventDisableTiming);
        cudaEventCreateWithFlags(&evC, cudaEventDisableTiming);
        cudaEventCreateWithFlags(&evD, cudaEventDisableTiming);
    }

    cudaMemcpyAsync(p_bkv,        bk, DMODEL * sizeof(float), cudaMemcpyDeviceToDevice);
    cudaMemcpyAsync(p_bkv + 1024, bv, DMODEL * sizeof(float), cudaMemcpyDeviceToDevice);

    // fork: wcvt on s1 || layernorm2 on main
    cudaEventRecord(evA, 0);
    cudaStreamWaitEvent(s1, evA, 0);
    wcvt_all_k<<<12288, 256, 0, s1>>>(Wq, Wk, Wv, Wo, W1, W2, wq, wkv, wo, w1, w2);
    layernorm2_k<<<MQ + MKV, 256>>>(query_tokens, point_features,
                                    ln_q_g, ln_q_b, ln_kv_g, ln_kv_b, qln, kvln);
    // join, then fork: Q proj + q rmsnorm on s1 || KV proj + kv rmsnorm on main
    cudaEventRecord(evB, s1);
    cudaStreamWaitEvent(0, evB, 0);
    cudaEventRecord(evC, 0);
    cudaStreamWaitEvent(s1, evC, 0);
    hgemm_k<3><<<dim3(DMODEL/128, MQ/128), 128, GEMM_SMEM_BYTES, s1>>>(
        qln, wq, bq, nullptr, nullptr, qp, MQ, DMODEL, DMODEL);
    rmsnorm_k<<<MQ, 256, 0, s1>>>(qp, rms_q_w, DMODEL);
    hgemm_k<3><<<dim3(KVLD/128, MKV/128), 128, GEMM_SMEM_BYTES>>>(
        kvln, wkv, p_bkv, nullptr, nullptr, kv, MKV, KVLD, DMODEL);
    rmsnorm_k<<<MKV, 256>>>(kv, rms_k_w, KVLD);
    cudaEventRecord(evD, s1);
    cudaStreamWaitEvent(0, evD, 0);

    flash_attn_mma<<<dim3(KQ/64, NHEAD, BATCH), 128, ATT_SMEM>>>(qp, kv, kv + 1024, ctx);

    hgemm_k<1><<<dim3(DMODEL/128, MQ/128), 128, GEMM_SMEM_BYTES>>>(
        ctx, wo, bo, query_tokens, p_out, nullptr, MQ, DMODEL, DMODEL);

    layernorm_h_k<<<MQ, 256>>>(p_out, ln_mlp_g, ln_mlp_b, hln);
    hgemm_k<2><<<dim3(DFF/128, MQ/128), 128, GEMM_SMEM_BYTES>>>(
        hln, w1, b1, nullptr, nullptr, m1, MQ, DFF, DMODEL);
    hgemm_k<1><<<dim3(DMODEL/128, MQ/128), 128, GEMM_SMEM_BYTES>>>(
        m1, w2, b2, p_out, out, nullptr, MQ, DMODEL, DFF);
}